// round 11
// baseline (speedup 1.0000x reference)
#include <cuda_runtime.h>
#include <cuda_fp16.h>
#include <cstdint>

// Problem constants
#define Bc   8
#define Sc   4096
#define Dc   1024
#define Mtot 32768            // B*S
#define NE   33554432         // Mtot*Dc elements
#define NC   32               // scan chunks
#define LC   128              // chunk length (NC*LC == Sc)

// -------- scratch (device globals: allocation-free) --------
__device__ __align__(16) float  g_p [NE];   // gate_x pre (fp32)
__device__ __align__(16) float  g_q [NE];   // gate_a pre -> a (fp32)
__device__ __align__(16) __half g_xh[NE];   // gelu(x) fp16
__device__ __align__(16) __half g_vh[NE];   // v fp16
__device__ __align__(16) __half g_uh[NE];   // u -> hf fp16 (in place)
__device__ __align__(16) __half g_ph[NE];   // hb fp16 (local then corrected)
__device__ __align__(16) __half g_Wh[6 * 1024 * 1024]; // frag-pair-packed fp16 weights
__device__ __align__(16) float g_cV [Bc*NC*Dc];   // fwd carries
__device__ __align__(16) float g_cI [Bc*NC*Dc];   // fwd prefixes
__device__ __align__(16) float g_cVb[Bc*NC*Dc];   // bwd carries
__device__ __align__(16) float g_cP [Bc*NC*Dc];   // bwd chunk products
__device__ __align__(16) float g_cIb[Bc*NC*Dc];   // bwd prefixes

// ================= helpers =================
__device__ __forceinline__ void mma16(float* c, const unsigned* a, const unsigned* b) {
    asm volatile(
        "mma.sync.aligned.m16n8k16.row.col.f32.f16.f16.f32 "
        "{%0,%1,%2,%3}, {%4,%5,%6,%7}, {%8,%9}, {%0,%1,%2,%3};\n"
        : "+f"(c[0]), "+f"(c[1]), "+f"(c[2]), "+f"(c[3])
        : "r"(a[0]), "r"(a[1]), "r"(a[2]), "r"(a[3]), "r"(b[0]), "r"(b[1]));
}
__device__ __forceinline__ float gelu1(float x) {
    const float c = 0.7978845608028654f;
    float t = tanhf(c * (x + 0.044715f * x * x * x));
    return 0.5f * x * (1.f + t);
}
__device__ __forceinline__ float sigmoidf(float x) { return 1.f / (1.f + expf(-x)); }
__device__ __forceinline__ uint32_t smem_u32(const void* p) {
    uint32_t a;
    asm("{ .reg .u64 t; cvta.to.shared.u64 t, %1; cvt.u32.u64 %0, t; }" : "=r"(a) : "l"(p));
    return a;
}
__device__ __forceinline__ void cpasync16(uint32_t sdst, const void* gsrc) {
    asm volatile("cp.async.cg.shared.global [%0], [%1], 16;\n" :: "r"(sdst), "l"(gsrc));
}

// ================= GEMM (fp16 mma.sync m16n8k16, 64x64 warp tiles, BK=64) ========
// CTA tile 128x128x64, 4 warps, warp tile 64x64, 3-stage cp.async, 2 CTAs/SM.
// As: fp16 [m][k] rows padded to 144B -> LDS.32 frags conflict-free.
// Bs: frag-pair-packed rows (ksj = kk*4+j), 128 n-entries of 8B
//     {B[k0][n],B[k0+1][n],B[k0+8][n],B[k0+9][n]}, k0 = kk*16 + 2j.
//     word8(ksj,n) = ksj*136 + (n ^ ((ksj&3)<<2)). One LDS.64 per B frag.
#define A_BYTES  (128 * 144)            // 18432
#define B_BYTES  (16 * 136 * 8)         // 17408
#define SET_B    (A_BYTES + B_BYTES)    // 35840
#define SMEMSZ   (3 * SET_B)            // 107520

// TWOB: grid.x in [0,16): xb = x&7 N-tile, sel = x>>3 picks (B1,C1,bias1)/(B2,C2,bias2)
// DUAL: K=2048 over (A1,B1) then (A2,B2); epilogue adds bias1+bias2+resid
// C1H/C2H: respective outputs stored as fp16
template <bool TWOB, bool DUAL, bool C1H, bool C2H>
__global__ __launch_bounds__(128, 2)
void hgemm(const __half* __restrict__ A1, const __half* __restrict__ A2,
           const __half* __restrict__ B1, const __half* __restrict__ B2,
           const float* __restrict__ bias1, const float* __restrict__ bias2,
           const float* __restrict__ resid,
           void* __restrict__ C1v, void* __restrict__ C2v)
{
    constexpr int NK = DUAL ? 32 : 16;       // K-tiles of 64
    extern __shared__ float smem[];
    const uint32_t sb = smem_u32(smem);
    const int tid  = threadIdx.x;
    const int lane = tid & 31;
    const int warp = tid >> 5;
    const int wm = warp & 1;        // M half (64 rows)
    const int wn = warp >> 1;       // N half (64 cols)

    const int xb  = TWOB ? (blockIdx.x & 7) : blockIdx.x;
    const int sel = TWOB ? (int)(blockIdx.x >> 3) : 0;
    const int m0 = blockIdx.y * 128;
    const int n0 = xb * 128;
    const __half* Bsel   = (TWOB && sel) ? B2 : B1;
    const float* biassel = (TWOB && sel) ? bias2 : bias1;

    float acc[4][8][4];
#pragma unroll
    for (int i = 0; i < 4; i++)
#pragma unroll
        for (int j = 0; j < 8; j++)
#pragma unroll
            for (int k = 0; k < 4; k++) acc[i][j][k] = 0.f;

    // ---- async tile issue (128 threads) ----
    auto issue = [&](int c) {
        const int slot = c % 3;
        const __half* Ap; const __half* Bp; int cl;
        if (DUAL && c >= 16) { Ap = A2; Bp = B2;   cl = c - 16; }
        else                 { Ap = A1; Bp = Bsel; cl = c; }
        const uint32_t sa = sb + slot * SET_B;
        const uint32_t sB = sa + A_BYTES;
        // A: 128 rows x 64 fp16 (128B) -> 144B-stride rows
#pragma unroll
        for (int i = 0; i < 8; i++) {
            int id = tid + i * 128;
            int r = id >> 3, kq = id & 7;
            cpasync16(sa + (uint32_t)(r * 144 + kq * 16),
                      Ap + (size_t)(m0 + r) * 1024 + cl * 64 + kq * 8);
        }
        // B: 16 packed rows x 128 n x 8B; global row stride 4096 halfs
#pragma unroll
        for (int i = 0; i < 8; i++) {
            int id = tid + i * 128;
            int ksj = id >> 6, ch = id & 63;
            uint32_t w8 = (uint32_t)(ksj * 136 + ((2 * ch) ^ ((ksj & 3) << 2)));
            cpasync16(sB + w8 * 8,
                      Bp + (size_t)(cl * 16 + ksj) * 4096 + (size_t)n0 * 4 + ch * 8);
        }
        asm volatile("cp.async.commit_group;\n");
    };

    auto compute = [&](int slot) {
        const uint32_t* Asw = (const uint32_t*)((const char*)smem + slot * SET_B);
        const uint2*    Bs2 = (const uint2*)((const char*)smem + slot * SET_B + A_BYTES);
        const int r0  = wm * 64 + (lane >> 2);
        const int j   = lane & 3;
        const int ccb = wn * 64 + (lane >> 2);
#pragma unroll
        for (int kk = 0; kk < 4; kk++) {
            unsigned af[4][4], bf[8][2];
#pragma unroll
            for (int mt = 0; mt < 4; mt++) {
                int r = r0 + mt * 16;
                int w0 = r * 36 + kk * 8 + j;
                int w1 = (r + 8) * 36 + kk * 8 + j;
                af[mt][0] = Asw[w0];
                af[mt][1] = Asw[w1];
                af[mt][2] = Asw[w0 + 4];
                af[mt][3] = Asw[w1 + 4];
            }
            const int rowb = (kk * 4 + j) * 136;
#pragma unroll
            for (int nt = 0; nt < 8; nt++) {
                int cc = ccb + nt * 8;
                uint2 bv = Bs2[rowb + (cc ^ (j << 2))];
                bf[nt][0] = bv.x;
                bf[nt][1] = bv.y;
            }
#pragma unroll
            for (int mt = 0; mt < 4; mt++)
#pragma unroll
                for (int nt = 0; nt < 8; nt++)
                    mma16(acc[mt][nt], af[mt], bf[nt]);
        }
    };

    issue(0);
    issue(1);
    for (int k = 0; k < NK; k++) {
        if (k < NK - 1) asm volatile("cp.async.wait_group 1;\n");
        else            asm volatile("cp.async.wait_group 0;\n");
        __syncthreads();
        if (k + 2 < NK) issue(k + 2);
        compute(k % 3);
    }

    // ---- epilogue ----
#pragma unroll
    for (int mt = 0; mt < 4; mt++) {
        int row = m0 + wm * 64 + mt * 16 + (lane >> 2);
#pragma unroll
        for (int nt = 0; nt < 8; nt++) {
            int col = n0 + wn * 64 + nt * 8 + (lane & 3) * 2;
            float b0 = biassel[col], b1 = biassel[col + 1];
            if (DUAL) { b0 += bias2[col]; b1 += bias2[col + 1]; }
            size_t i0 = (size_t)row * 1024 + col;
            size_t i1 = i0 + (size_t)8 * 1024;
            float2 v0 = make_float2(acc[mt][nt][0] + b0, acc[mt][nt][1] + b1);
            float2 v1 = make_float2(acc[mt][nt][2] + b0, acc[mt][nt][3] + b1);
            if (DUAL) {
                float2 x0 = *reinterpret_cast<const float2*>(&resid[i0]);
                float2 x1 = *reinterpret_cast<const float2*>(&resid[i1]);
                v0.x += x0.x; v0.y += x0.y; v1.x += x1.x; v1.y += x1.y;
            }
            const bool useC2 = TWOB && sel;
            const bool asH = useC2 ? C2H : C1H;
            void* Cp = useC2 ? C2v : C1v;
            if (asH) {
                __half* Ch = (__half*)Cp;
                *reinterpret_cast<__half2*>(&Ch[i0]) = __floats2half2_rn(v0.x, v0.y);
                *reinterpret_cast<__half2*>(&Ch[i1]) = __floats2half2_rn(v1.x, v1.y);
            } else {
                float* Cf = (float*)Cp;
                *reinterpret_cast<float2*>(&Cf[i0]) = v0;
                *reinterpret_cast<float2*>(&Cf[i1]) = v1;
            }
        }
    }
}

// ================= weight frag-pair pack to fp16 =================
__global__ void wpack(const float* __restrict__ w0, const float* __restrict__ w1,
                      const float* __restrict__ w2, const float* __restrict__ w3,
                      const float* __restrict__ w4, const float* __restrict__ w5)
{
    const float* srcs[6] = {w0, w1, w2, w3, w4, w5};
    const float* src = srcs[blockIdx.y];
    __half* dst = g_Wh + (size_t)blockIdx.y * 1048576;
    const int kg = blockIdx.x;          // 0..63
    const int t = threadIdx.x;          // 0..255
#pragma unroll
    for (int j = 0; j < 4; j++) {
#pragma unroll
        for (int nn = 0; nn < 4; nn++) {
            int n = nn * 256 + t;
            float f0 = src[(size_t)(kg * 16 + 2 * j    ) * 1024 + n];
            float f1 = src[(size_t)(kg * 16 + 2 * j + 1) * 1024 + n];
            float f2 = src[(size_t)(kg * 16 + 2 * j + 8) * 1024 + n];
            float f3 = src[(size_t)(kg * 16 + 2 * j + 9) * 1024 + n];
            __half2 p0 = __floats2half2_rn(f0, f1);
            __half2 p1 = __floats2half2_rn(f2, f3);
            uint2 o;
            o.x = *reinterpret_cast<uint32_t*>(&p0);
            o.y = *reinterpret_cast<uint32_t*>(&p1);
            *reinterpret_cast<uint2*>(&dst[((size_t)(kg * 4 + j) * 1024 + n) * 4]) = o;
        }
    }
}

// ================= elementwise =================
__global__ void ew_gelu(const float* __restrict__ x) {
    int i = blockIdx.x * 256 + threadIdx.x;
    float4 v = reinterpret_cast<const float4*>(x)[i];
    __half2 h0 = __floats2half2_rn(gelu1(v.x), gelu1(v.y));
    __half2 h1 = __floats2half2_rn(gelu1(v.z), gelu1(v.w));
    uint2 o;
    o.x = *reinterpret_cast<uint32_t*>(&h0);
    o.y = *reinterpret_cast<uint32_t*>(&h1);
    reinterpret_cast<uint2*>(g_xh)[i] = o;
}

__device__ __forceinline__ float4 h2tof4(uint2 r) {
    __half2 h0 = *reinterpret_cast<__half2*>(&r.x);
    __half2 h1 = *reinterpret_cast<__half2*>(&r.y);
    return make_float4(__low2float(h0), __high2float(h0),
                       __low2float(h1), __high2float(h1));
}
__device__ __forceinline__ uint2 f4toh2(float4 v) {
    __half2 h0 = __floats2half2_rn(v.x, v.y);
    __half2 h1 = __floats2half2_rn(v.z, v.w);
    uint2 o;
    o.x = *reinterpret_cast<uint32_t*>(&h0);
    o.y = *reinterpret_cast<uint32_t*>(&h1);
    return o;
}

// ================= scans (float4 over d; fp16 state buffers) =====================
// phase 1: local chunk scans. grid (NC, 16): y<8 -> fwd (b=y), y>=8 -> bwd (b=y-8)
__global__ void scan1(const float* __restrict__ a_fwd, const float* __restrict__ a_param) {
    const int d4 = threadIdx.x;             // 0..255
    const int c = blockIdx.x;
    const int zz = blockIdx.y;
    if (zz < 8) {
        const int b = zz;
        float4 a = reinterpret_cast<const float4*>(a_fwd)[d4];
        int idx = ((b * Sc + c * LC) * Dc) / 4 + d4;
        float4 h = make_float4(0.f, 0.f, 0.f, 0.f);
#pragma unroll 4
        for (int t = 0; t < LC; t++) {
            float4 uv = h2tof4(reinterpret_cast<const uint2*>(g_uh)[idx]);
            h.x = fmaf(a.x, h.x, uv.x); h.y = fmaf(a.y, h.y, uv.y);
            h.z = fmaf(a.z, h.z, uv.z); h.w = fmaf(a.w, h.w, uv.w);
            reinterpret_cast<uint2*>(g_uh)[idx] = f4toh2(h);
            idx += 256;
        }
        reinterpret_cast<float4*>(g_cV)[(b * NC + c) * 256 + d4] = h;
    } else {
        const int b = zz - 8;
        float4 ap = reinterpret_cast<const float4*>(a_param)[d4];
        float4 sp = make_float4(log1pf(expf(ap.x)), log1pf(expf(ap.y)),
                                log1pf(expf(ap.z)), log1pf(expf(ap.w)));
        int idx = ((b * Sc + c * LC + LC - 1) * Dc) / 4 + d4;
        float4 h = make_float4(0.f, 0.f, 0.f, 0.f);
        float4 P = make_float4(1.f, 1.f, 1.f, 1.f);
#pragma unroll 4
        for (int t = 0; t < LC; t++) {
            float4 pv = reinterpret_cast<const float4*>(g_p)[idx];
            float4 qv = reinterpret_cast<const float4*>(g_q)[idx];
            float4 vv = h2tof4(reinterpret_cast<const uint2*>(g_vh)[idx]);
            float4 ao;
#define GB(PV,QV,VV,SP,H,PP,AO) { \
            float gx = sigmoidf(PV); float ga = sigmoidf(QV); \
            float a_ = expf(-8.f * ga * (SP)); \
            float si = sqrtf(fmaxf(1.f - a_*a_, 0.f)) * gx * (VV); \
            H = fmaf(a_, H, si); PP *= a_; AO = a_; }
            GB(pv.x, qv.x, vv.x, sp.x, h.x, P.x, ao.x)
            GB(pv.y, qv.y, vv.y, sp.y, h.y, P.y, ao.y)
            GB(pv.z, qv.z, vv.z, sp.z, h.z, P.z, ao.z)
            GB(pv.w, qv.w, vv.w, sp.w, h.w, P.w, ao.w)
#undef GB
            reinterpret_cast<float4*>(g_q)[idx] = ao;
            reinterpret_cast<uint2*>(g_ph)[idx] = f4toh2(h);
            idx -= 256;
        }
        int o = (b * NC + c) * 256 + d4;
        reinterpret_cast<float4*>(g_cVb)[o] = h;
        reinterpret_cast<float4*>(g_cP)[o] = P;
    }
}

// phase 2: carry prefix across chunks. 64 blocks x 256: first half fwd, second bwd
__global__ void scan2(const float* __restrict__ a_fwd) {
    int g = blockIdx.x * 256 + threadIdx.x;
    if (g < 8192) {
        int b = g >> 10, d = g & 1023;
        float a = a_fwd[d];
        float aL = a;
#pragma unroll
        for (int i = 0; i < 7; i++) aL *= aL;     // a^128
        float H = 0.f;
        for (int c = 0; c < NC; c++) {
            int o = (b * NC + c) * Dc + d;
            float cv = g_cV[o];
            g_cI[o] = H;
            H = fmaf(aL, H, cv);
        }
    } else {
        g -= 8192;
        int b = g >> 10, d = g & 1023;
        float H = 0.f;
        for (int c = NC - 1; c >= 0; c--) {
            int o = (b * NC + c) * Dc + d;
            float cv = g_cVb[o], cp = g_cP[o];
            g_cIb[o] = H;
            H = fmaf(cp, H, cv);
        }
    }
}

// phase 3: apply carries in the fp16 buffers. grid (NC, 16)
__global__ void scan3(const float* __restrict__ a_fwd) {
    const int d4 = threadIdx.x;
    const int c = blockIdx.x;
    const int zz = blockIdx.y;
    if (zz < 8) {
        if (c == 0) return;                        // chunk 0: local == final
        const int b = zz;
        float4 a = reinterpret_cast<const float4*>(a_fwd)[d4];
        float4 H = reinterpret_cast<const float4*>(g_cI)[(b * NC + c) * 256 + d4];
        int idx = ((b * Sc + c * LC) * Dc) / 4 + d4;
        float4 pw = a;
#pragma unroll 4
        for (int t = 0; t < LC; t++) {
            float4 uv = h2tof4(reinterpret_cast<const uint2*>(g_uh)[idx]);
            uv.x = fmaf(pw.x, H.x, uv.x); uv.y = fmaf(pw.y, H.y, uv.y);
            uv.z = fmaf(pw.z, H.z, uv.z); uv.w = fmaf(pw.w, H.w, uv.w);
            reinterpret_cast<uint2*>(g_uh)[idx] = f4toh2(uv);
            pw.x *= a.x; pw.y *= a.y; pw.z *= a.z; pw.w *= a.w;
            idx += 256;
        }
    } else {
        if (c == NC - 1) return;                   // last chunk: local == final
        const int b = zz - 8;
        float4 H = reinterpret_cast<const float4*>(g_cIb)[(b * NC + c) * 256 + d4];
        int idx = ((b * Sc + c * LC + LC - 1) * Dc) / 4 + d4;
        float4 P = make_float4(1.f, 1.f, 1.f, 1.f);
#pragma unroll 4
        for (int t = 0; t < LC; t++) {
            float4 at = reinterpret_cast<const float4*>(g_q)[idx];
            float4 pv = h2tof4(reinterpret_cast<const uint2*>(g_ph)[idx]);
            P.x *= at.x; P.y *= at.y; P.z *= at.z; P.w *= at.w;
            pv.x = fmaf(P.x, H.x, pv.x); pv.y = fmaf(P.y, H.y, pv.y);
            pv.z = fmaf(P.z, H.z, pv.z); pv.w = fmaf(P.w, H.w, pv.w);
            reinterpret_cast<uint2*>(g_ph)[idx] = f4toh2(pv);
            idx -= 256;
        }
    }
}

// ================= launch =================
extern "C" void kernel_launch(void* const* d_in, const int* in_sizes, int n_in,
                              void* d_out, int out_size)
{
    const float* x       = (const float*)d_in[0];
    const float* a_fwd   = (const float*)d_in[1];
    const float* Wf1     = (const float*)d_in[2];
    const float* bf1     = (const float*)d_in[3];
    const float* Wf2     = (const float*)d_in[4];
    const float* bf2     = (const float*)d_in[5];
    const float* Wbx     = (const float*)d_in[6];
    const float* bbx     = (const float*)d_in[7];
    const float* Wgx     = (const float*)d_in[8];
    const float* bgx     = (const float*)d_in[9];
    const float* Wga     = (const float*)d_in[10];
    const float* bga     = (const float*)d_in[11];
    const float* a_param = (const float*)d_in[12];
    const float* Wb2     = (const float*)d_in[13];
    const float* bb2     = (const float*)d_in[14];
    float* out = (float*)d_out;

    float *p, *q;
    __half *xh, *vh, *uh, *ph, *wh;
    cudaGetSymbolAddress((void**)&p,  g_p);
    cudaGetSymbolAddress((void**)&q,  g_q);
    cudaGetSymbolAddress((void**)&xh, g_xh);
    cudaGetSymbolAddress((void**)&vh, g_vh);
    cudaGetSymbolAddress((void**)&uh, g_uh);
    cudaGetSymbolAddress((void**)&ph, g_ph);
    cudaGetSymbolAddress((void**)&wh, g_Wh);
    const __half* Wh_f1 = wh + 0u * 1048576;
    const __half* Wh_bx = wh + 1u * 1048576;
    const __half* Wh_gx = wh + 2u * 1048576;
    const __half* Wh_ga = wh + 3u * 1048576;
    const __half* Wh_f2 = wh + 4u * 1048576;
    const __half* Wh_b2 = wh + 5u * 1048576;

    cudaFuncSetAttribute(hgemm<true,  false, true,  true>,  cudaFuncAttributeMaxDynamicSharedMemorySize, SMEMSZ);
    cudaFuncSetAttribute(hgemm<true,  false, false, false>, cudaFuncAttributeMaxDynamicSharedMemorySize, SMEMSZ);
    cudaFuncSetAttribute(hgemm<false, true,  false, false>, cudaFuncAttributeMaxDynamicSharedMemorySize, SMEMSZ);

    dim3 gp(16, 256);         // pair: (8 N-tiles x 2 sel) x 256 M-tiles
    dim3 gf(8, 256);          // final
    dim3 gsc(NC, 16);         // chunks x (8 fwd + 8 bwd)

    // pack weights to fp16 fragment-pair layout
    wpack<<<dim3(64, 6), 256>>>(Wf1, Wbx, Wgx, Wga, Wf2, Wb2);
    // xh = fp16(gelu(x))
    ew_gelu<<<NE / 4 / 256, 256>>>(x);
    // uh = fp16(xh@Wf1+bf1) ; vh = fp16(xh@Wbx+bbx)
    hgemm<true, false, true, true><<<gp, 128, SMEMSZ>>>(xh, nullptr, Wh_f1, Wh_bx, bf1, bbx, nullptr, (void*)uh, (void*)vh);
    // p = vh@Wgx+bgx ; q = vh@Wga+bga (both fp32)
    hgemm<true, false, false, false><<<gp, 128, SMEMSZ>>>(vh, nullptr, Wh_gx, Wh_ga, bgx, bga, nullptr, (void*)p, (void*)q);
    // scans: local (fwd in-place on uh; fused gates + bwd -> ph/q), carries, correction
    scan1<<<gsc, 256>>>(a_fwd, a_param);
    scan2<<<64, 256>>>(a_fwd);
    scan3<<<gsc, 256>>>(a_fwd);
    // out = hf@Wf2 + hb@Wb2 + bf2 + bb2 + x
    hgemm<false, true, false, false><<<gf, 128, SMEMSZ>>>(uh, ph, Wh_f2, Wh_b2, bf2, bb2, x, (void*)out, nullptr);
}

// round 13
// speedup vs baseline: 1.4855x; 1.4855x over previous
#include <cuda_runtime.h>
#include <cuda_fp16.h>
#include <cstdint>

// Problem constants
#define Bc   8
#define Sc   4096
#define Dc   1024
#define Mtot 32768            // B*S
#define NE   33554432         // Mtot*Dc elements
#define NC   32               // scan chunks
#define LC   128              // chunk length (NC*LC == Sc)

// -------- scratch (device globals: allocation-free) --------
__device__ __align__(16) float  g_u [NE];   // u (fp32, GEMM1 out, read-only in scans)
__device__ __align__(16) float  g_p [NE];   // gate_x pre (fp32)
__device__ __align__(16) float  g_q [NE];   // gate_a pre -> a (fp32)
__device__ __align__(16) __half g_xh[NE];   // gelu(x) fp16
__device__ __align__(16) __half g_vh[NE];   // v fp16
__device__ __align__(16) __half g_uh[NE];   // hf fp16 (local then corrected)
__device__ __align__(16) __half g_ph[NE];   // hb fp16 (local then corrected)
__device__ __align__(16) __half g_Wh[6 * 1024 * 1024]; // frag-pair-packed fp16 weights
__device__ __align__(16) float g_cV [Bc*NC*Dc];   // fwd carries
__device__ __align__(16) float g_cI [Bc*NC*Dc];   // fwd prefixes
__device__ __align__(16) float g_cVb[Bc*NC*Dc];   // bwd carries
__device__ __align__(16) float g_cP [Bc*NC*Dc];   // bwd chunk products
__device__ __align__(16) float g_cIb[Bc*NC*Dc];   // bwd prefixes

// ================= helpers =================
__device__ __forceinline__ void mma16(float* c, const unsigned* a, const unsigned* b) {
    asm volatile(
        "mma.sync.aligned.m16n8k16.row.col.f32.f16.f16.f32 "
        "{%0,%1,%2,%3}, {%4,%5,%6,%7}, {%8,%9}, {%0,%1,%2,%3};\n"
        : "+f"(c[0]), "+f"(c[1]), "+f"(c[2]), "+f"(c[3])
        : "r"(a[0]), "r"(a[1]), "r"(a[2]), "r"(a[3]), "r"(b[0]), "r"(b[1]));
}
__device__ __forceinline__ float gelu1(float x) {
    const float c = 0.7978845608028654f;
    float t = tanhf(c * (x + 0.044715f * x * x * x));
    return 0.5f * x * (1.f + t);
}
__device__ __forceinline__ float sigmoidf(float x) { return 1.f / (1.f + expf(-x)); }
__device__ __forceinline__ uint32_t smem_u32(const void* p) {
    uint32_t a;
    asm("{ .reg .u64 t; cvta.to.shared.u64 t, %1; cvt.u32.u64 %0, t; }" : "=r"(a) : "l"(p));
    return a;
}
__device__ __forceinline__ void cpasync16(uint32_t sdst, const void* gsrc) {
    asm volatile("cp.async.cg.shared.global [%0], [%1], 16;\n" :: "r"(sdst), "l"(gsrc));
}
__device__ __forceinline__ float4 h2tof4(uint2 r) {
    __half2 h0 = *reinterpret_cast<__half2*>(&r.x);
    __half2 h1 = *reinterpret_cast<__half2*>(&r.y);
    return make_float4(__low2float(h0), __high2float(h0),
                       __low2float(h1), __high2float(h1));
}
__device__ __forceinline__ uint2 f4toh2(float4 v) {
    __half2 h0 = __floats2half2_rn(v.x, v.y);
    __half2 h1 = __floats2half2_rn(v.z, v.w);
    uint2 o;
    o.x = *reinterpret_cast<uint32_t*>(&h0);
    o.y = *reinterpret_cast<uint32_t*>(&h1);
    return o;
}

// ================= GEMM (fp16 mma.sync m16n8k16, 64x64 warp tiles, BK=64) ========
// CTA tile 128x128x64, 4 warps, warp tile 64x64, 3-stage cp.async, 2 CTAs/SM.
// As: fp16 [m][k] rows padded to 144B -> LDS.32 frags conflict-free.
// Bs: frag-pair-packed rows (ksj = kk*4+j), 128 n-entries of 8B
//     {B[k0][n],B[k0+1][n],B[k0+8][n],B[k0+9][n]}, k0 = kk*16 + 2j.
//     word8(ksj,n) = ksj*136 + (n ^ ((ksj&3)<<2)). One LDS.64 per B frag.
#define A_BYTES  (128 * 144)            // 18432
#define B_BYTES  (16 * 136 * 8)         // 17408
#define SET_B    (A_BYTES + B_BYTES)    // 35840
#define SMEMSZ   (3 * SET_B)            // 107520

// TWOB: grid.x in [0,16): xb = x&7 N-tile, sel = x>>3 picks (B1,C1,bias1)/(B2,C2,bias2)
// DUAL: K=2048 over (A1,B1) then (A2,B2); epilogue adds bias1+bias2+resid
// C2H : C2 output stored as fp16
template <bool TWOB, bool DUAL, bool C2H>
__global__ __launch_bounds__(128, 2)
void hgemm(const __half* __restrict__ A1, const __half* __restrict__ A2,
           const __half* __restrict__ B1, const __half* __restrict__ B2,
           const float* __restrict__ bias1, const float* __restrict__ bias2,
           const float* __restrict__ resid,
           float* __restrict__ C1, void* __restrict__ C2v)
{
    constexpr int NK = DUAL ? 32 : 16;       // K-tiles of 64
    extern __shared__ float smem[];
    const uint32_t sb = smem_u32(smem);
    const int tid  = threadIdx.x;
    const int lane = tid & 31;
    const int warp = tid >> 5;
    const int wm = warp & 1;        // M half (64 rows)
    const int wn = warp >> 1;       // N half (64 cols)

    const int xb  = TWOB ? (blockIdx.x & 7) : blockIdx.x;
    const int sel = TWOB ? (int)(blockIdx.x >> 3) : 0;
    const int m0 = blockIdx.y * 128;
    const int n0 = xb * 128;
    const __half* Bsel   = (TWOB && sel) ? B2 : B1;
    const float* biassel = (TWOB && sel) ? bias2 : bias1;

    float acc[4][8][4];
#pragma unroll
    for (int i = 0; i < 4; i++)
#pragma unroll
        for (int j = 0; j < 8; j++)
#pragma unroll
            for (int k = 0; k < 4; k++) acc[i][j][k] = 0.f;

    // ---- async tile issue (128 threads) ----
    auto issue = [&](int c) {
        const int slot = c % 3;
        const __half* Ap; const __half* Bp; int cl;
        if (DUAL && c >= 16) { Ap = A2; Bp = B2;   cl = c - 16; }
        else                 { Ap = A1; Bp = Bsel; cl = c; }
        const uint32_t sa = sb + slot * SET_B;
        const uint32_t sB = sa + A_BYTES;
        // A: 128 rows x 64 fp16 (128B) -> 144B-stride rows
#pragma unroll
        for (int i = 0; i < 8; i++) {
            int id = tid + i * 128;
            int r = id >> 3, kq = id & 7;
            cpasync16(sa + (uint32_t)(r * 144 + kq * 16),
                      Ap + (size_t)(m0 + r) * 1024 + cl * 64 + kq * 8);
        }
        // B: 16 packed rows x 128 n x 8B; global row stride 4096 halfs
#pragma unroll
        for (int i = 0; i < 8; i++) {
            int id = tid + i * 128;
            int ksj = id >> 6, ch = id & 63;
            uint32_t w8 = (uint32_t)(ksj * 136 + ((2 * ch) ^ ((ksj & 3) << 2)));
            cpasync16(sB + w8 * 8,
                      Bp + (size_t)(cl * 16 + ksj) * 4096 + (size_t)n0 * 4 + ch * 8);
        }
        asm volatile("cp.async.commit_group;\n");
    };

    auto compute = [&](int slot) {
        const uint32_t* Asw = (const uint32_t*)((const char*)smem + slot * SET_B);
        const uint2*    Bs2 = (const uint2*)((const char*)smem + slot * SET_B + A_BYTES);
        const int r0  = wm * 64 + (lane >> 2);
        const int j   = lane & 3;
        const int ccb = wn * 64 + (lane >> 2);
#pragma unroll
        for (int kk = 0; kk < 4; kk++) {
            unsigned af[4][4], bf[8][2];
#pragma unroll
            for (int mt = 0; mt < 4; mt++) {
                int r = r0 + mt * 16;
                int w0 = r * 36 + kk * 8 + j;
                int w1 = (r + 8) * 36 + kk * 8 + j;
                af[mt][0] = Asw[w0];
                af[mt][1] = Asw[w1];
                af[mt][2] = Asw[w0 + 4];
                af[mt][3] = Asw[w1 + 4];
            }
            const int rowb = (kk * 4 + j) * 136;
#pragma unroll
            for (int nt = 0; nt < 8; nt++) {
                int cc = ccb + nt * 8;
                uint2 bv = Bs2[rowb + (cc ^ (j << 2))];
                bf[nt][0] = bv.x;
                bf[nt][1] = bv.y;
            }
#pragma unroll
            for (int mt = 0; mt < 4; mt++)
#pragma unroll
                for (int nt = 0; nt < 8; nt++)
                    mma16(acc[mt][nt], af[mt], bf[nt]);
        }
    };

    issue(0);
    issue(1);
    for (int k = 0; k < NK; k++) {
        if (k < NK - 1) asm volatile("cp.async.wait_group 1;\n");
        else            asm volatile("cp.async.wait_group 0;\n");
        __syncthreads();
        if (k + 2 < NK) issue(k + 2);
        compute(k % 3);
    }

    // ---- epilogue ----
#pragma unroll
    for (int mt = 0; mt < 4; mt++) {
        int row = m0 + wm * 64 + mt * 16 + (lane >> 2);
#pragma unroll
        for (int nt = 0; nt < 8; nt++) {
            int col = n0 + wn * 64 + nt * 8 + (lane & 3) * 2;
            float b0 = biassel[col], b1 = biassel[col + 1];
            if (DUAL) { b0 += bias2[col]; b1 += bias2[col + 1]; }
            size_t i0 = (size_t)row * 1024 + col;
            size_t i1 = i0 + (size_t)8 * 1024;
            float2 v0 = make_float2(acc[mt][nt][0] + b0, acc[mt][nt][1] + b1);
            float2 v1 = make_float2(acc[mt][nt][2] + b0, acc[mt][nt][3] + b1);
            if (DUAL) {
                float2 x0 = *reinterpret_cast<const float2*>(&resid[i0]);
                float2 x1 = *reinterpret_cast<const float2*>(&resid[i1]);
                v0.x += x0.x; v0.y += x0.y; v1.x += x1.x; v1.y += x1.y;
            }
            if (TWOB && sel) {
                if (C2H) {
                    __half* C2h = (__half*)C2v;
                    *reinterpret_cast<__half2*>(&C2h[i0]) = __floats2half2_rn(v0.x, v0.y);
                    *reinterpret_cast<__half2*>(&C2h[i1]) = __floats2half2_rn(v1.x, v1.y);
                } else {
                    float* C2f = (float*)C2v;
                    *reinterpret_cast<float2*>(&C2f[i0]) = v0;
                    *reinterpret_cast<float2*>(&C2f[i1]) = v1;
                }
            } else {
                *reinterpret_cast<float2*>(&C1[i0]) = v0;
                *reinterpret_cast<float2*>(&C1[i1]) = v1;
            }
        }
    }
}

// ================= weight frag-pair pack to fp16 =================
__global__ void wpack(const float* __restrict__ w0, const float* __restrict__ w1,
                      const float* __restrict__ w2, const float* __restrict__ w3,
                      const float* __restrict__ w4, const float* __restrict__ w5)
{
    const float* srcs[6] = {w0, w1, w2, w3, w4, w5};
    const float* src = srcs[blockIdx.y];
    __half* dst = g_Wh + (size_t)blockIdx.y * 1048576;
    const int kg = blockIdx.x;          // 0..63
    const int t = threadIdx.x;          // 0..255
#pragma unroll
    for (int j = 0; j < 4; j++) {
#pragma unroll
        for (int nn = 0; nn < 4; nn++) {
            int n = nn * 256 + t;
            float f0 = src[(size_t)(kg * 16 + 2 * j    ) * 1024 + n];
            float f1 = src[(size_t)(kg * 16 + 2 * j + 1) * 1024 + n];
            float f2 = src[(size_t)(kg * 16 + 2 * j + 8) * 1024 + n];
            float f3 = src[(size_t)(kg * 16 + 2 * j + 9) * 1024 + n];
            __half2 p0 = __floats2half2_rn(f0, f1);
            __half2 p1 = __floats2half2_rn(f2, f3);
            uint2 o;
            o.x = *reinterpret_cast<uint32_t*>(&p0);
            o.y = *reinterpret_cast<uint32_t*>(&p1);
            *reinterpret_cast<uint2*>(&dst[((size_t)(kg * 4 + j) * 1024 + n) * 4]) = o;
        }
    }
}

// ================= elementwise =================
__global__ void ew_gelu(const float* __restrict__ x) {
    int i = blockIdx.x * 256 + threadIdx.x;
    float4 v = reinterpret_cast<const float4*>(x)[i];
    __half2 h0 = __floats2half2_rn(gelu1(v.x), gelu1(v.y));
    __half2 h1 = __floats2half2_rn(gelu1(v.z), gelu1(v.w));
    uint2 o;
    o.x = *reinterpret_cast<uint32_t*>(&h0);
    o.y = *reinterpret_cast<uint32_t*>(&h1);
    reinterpret_cast<uint2*>(g_xh)[i] = o;
}

// ================= scans (float4 over d; fp16 local h emit) ======================
// phase 1: local chunk scans. grid (NC, 16): y<8 -> fwd (b=y), y>=8 -> bwd (b=y-8)
__global__ void scan1(const float* __restrict__ a_fwd, const float* __restrict__ a_param) {
    const int d4 = threadIdx.x;             // 0..255
    const int c = blockIdx.x;
    const int zz = blockIdx.y;
    if (zz < 8) {
        const int b = zz;
        float4 a = reinterpret_cast<const float4*>(a_fwd)[d4];
        int idx = ((b * Sc + c * LC) * Dc) / 4 + d4;
        float4 h = make_float4(0.f, 0.f, 0.f, 0.f);
#pragma unroll 4
        for (int t = 0; t < LC; t++) {
            float4 uv = reinterpret_cast<const float4*>(g_u)[idx];
            h.x = fmaf(a.x, h.x, uv.x); h.y = fmaf(a.y, h.y, uv.y);
            h.z = fmaf(a.z, h.z, uv.z); h.w = fmaf(a.w, h.w, uv.w);
            reinterpret_cast<uint2*>(g_uh)[idx] = f4toh2(h);
            idx += 256;
        }
        reinterpret_cast<float4*>(g_cV)[(b * NC + c) * 256 + d4] = h;
    } else {
        const int b = zz - 8;
        float4 ap = reinterpret_cast<const float4*>(a_param)[d4];
        float4 sp = make_float4(log1pf(expf(ap.x)), log1pf(expf(ap.y)),
                                log1pf(expf(ap.z)), log1pf(expf(ap.w)));
        int idx = ((b * Sc + c * LC + LC - 1) * Dc) / 4 + d4;
        float4 h = make_float4(0.f, 0.f, 0.f, 0.f);
        float4 P = make_float4(1.f, 1.f, 1.f, 1.f);
#pragma unroll 4
        for (int t = 0; t < LC; t++) {
            float4 pv = reinterpret_cast<const float4*>(g_p)[idx];
            float4 qv = reinterpret_cast<const float4*>(g_q)[idx];
            float4 vv = h2tof4(reinterpret_cast<const uint2*>(g_vh)[idx]);
            float4 ao;
#define GB(PV,QV,VV,SP,H,PP,AO) { \
            float gx = sigmoidf(PV); float ga = sigmoidf(QV); \
            float a_ = expf(-8.f * ga * (SP)); \
            float si = sqrtf(fmaxf(1.f - a_*a_, 0.f)) * gx * (VV); \
            H = fmaf(a_, H, si); PP *= a_; AO = a_; }
            GB(pv.x, qv.x, vv.x, sp.x, h.x, P.x, ao.x)
            GB(pv.y, qv.y, vv.y, sp.y, h.y, P.y, ao.y)
            GB(pv.z, qv.z, vv.z, sp.z, h.z, P.z, ao.z)
            GB(pv.w, qv.w, vv.w, sp.w, h.w, P.w, ao.w)
#undef GB
            reinterpret_cast<float4*>(g_q)[idx] = ao;
            reinterpret_cast<uint2*>(g_ph)[idx] = f4toh2(h);
            idx -= 256;
        }
        int o = (b * NC + c) * 256 + d4;
        reinterpret_cast<float4*>(g_cVb)[o] = h;
        reinterpret_cast<float4*>(g_cP)[o] = P;
    }
}

// phase 2: carry prefix across chunks. 64 blocks x 256: first half fwd, second bwd
__global__ void scan2(const float* __restrict__ a_fwd) {
    int g = blockIdx.x * 256 + threadIdx.x;
    if (g < 8192) {
        int b = g >> 10, d = g & 1023;
        float a = a_fwd[d];
        float aL = a;
#pragma unroll
        for (int i = 0; i < 7; i++) aL *= aL;     // a^128
        float H = 0.f;
        for (int c = 0; c < NC; c++) {
            int o = (b * NC + c) * Dc + d;
            float cv = g_cV[o];
            g_cI[o] = H;
            H = fmaf(aL, H, cv);
        }
    } else {
        g -= 8192;
        int b = g >> 10, d = g & 1023;
        float H = 0.f;
        for (int c = NC - 1; c >= 0; c--) {
            int o = (b * NC + c) * Dc + d;
            float cv = g_cVb[o], cp = g_cP[o];
            g_cIb[o] = H;
            H = fmaf(cp, H, cv);
        }
    }
}

// phase 3: apply carries in the fp16 buffers. grid (NC, 16)
__global__ void scan3(const float* __restrict__ a_fwd) {
    const int d4 = threadIdx.x;
    const int c = blockIdx.x;
    const int zz = blockIdx.y;
    if (zz < 8) {
        if (c == 0) return;                        // chunk 0: local == final
        const int b = zz;
        float4 a = reinterpret_cast<const float4*>(a_fwd)[d4];
        float4 H = reinterpret_cast<const float4*>(g_cI)[(b * NC + c) * 256 + d4];
        int idx = ((b * Sc + c * LC) * Dc) / 4 + d4;
        float4 pw = a;
#pragma unroll 4
        for (int t = 0; t < LC; t++) {
            float4 uv = h2tof4(reinterpret_cast<const uint2*>(g_uh)[idx]);
            uv.x = fmaf(pw.x, H.x, uv.x); uv.y = fmaf(pw.y, H.y, uv.y);
            uv.z = fmaf(pw.z, H.z, uv.z); uv.w = fmaf(pw.w, H.w, uv.w);
            reinterpret_cast<uint2*>(g_uh)[idx] = f4toh2(uv);
            pw.x *= a.x; pw.y *= a.y; pw.z *= a.z; pw.w *= a.w;
            idx += 256;
        }
    } else {
        if (c == NC - 1) return;                   // last chunk: local == final
        const int b = zz - 8;
        float4 H = reinterpret_cast<const float4*>(g_cIb)[(b * NC + c) * 256 + d4];
        int idx = ((b * Sc + c * LC + LC - 1) * Dc) / 4 + d4;
        float4 P = make_float4(1.f, 1.f, 1.f, 1.f);
#pragma unroll 4
        for (int t = 0; t < LC; t++) {
            float4 at = reinterpret_cast<const float4*>(g_q)[idx];
            float4 pv = h2tof4(reinterpret_cast<const uint2*>(g_ph)[idx]);
            P.x *= at.x; P.y *= at.y; P.z *= at.z; P.w *= at.w;
            pv.x = fmaf(P.x, H.x, pv.x); pv.y = fmaf(P.y, H.y, pv.y);
            pv.z = fmaf(P.z, H.z, pv.z); pv.w = fmaf(P.w, H.w, pv.w);
            reinterpret_cast<uint2*>(g_ph)[idx] = f4toh2(pv);
            idx -= 256;
        }
    }
}

// ================= launch =================
extern "C" void kernel_launch(void* const* d_in, const int* in_sizes, int n_in,
                              void* d_out, int out_size)
{
    const float* x       = (const float*)d_in[0];
    const float* a_fwd   = (const float*)d_in[1];
    const float* Wf1     = (const float*)d_in[2];
    const float* bf1     = (const float*)d_in[3];
    const float* Wf2     = (const float*)d_in[4];
    const float* bf2     = (const float*)d_in[5];
    const float* Wbx     = (const float*)d_in[6];
    const float* bbx     = (const float*)d_in[7];
    const float* Wgx     = (const float*)d_in[8];
    const float* bgx     = (const float*)d_in[9];
    const float* Wga     = (const float*)d_in[10];
    const float* bga     = (const float*)d_in[11];
    const float* a_param = (const float*)d_in[12];
    const float* Wb2     = (const float*)d_in[13];
    const float* bb2     = (const float*)d_in[14];
    float* out = (float*)d_out;

    float *u, *p, *q;
    __half *xh, *vh, *uh, *ph, *wh;
    cudaGetSymbolAddress((void**)&u,  g_u);
    cudaGetSymbolAddress((void**)&p,  g_p);
    cudaGetSymbolAddress((void**)&q,  g_q);
    cudaGetSymbolAddress((void**)&xh, g_xh);
    cudaGetSymbolAddress((void**)&vh, g_vh);
    cudaGetSymbolAddress((void**)&uh, g_uh);
    cudaGetSymbolAddress((void**)&ph, g_ph);
    cudaGetSymbolAddress((void**)&wh, g_Wh);
    const __half* Wh_f1 = wh + 0u * 1048576;
    const __half* Wh_bx = wh + 1u * 1048576;
    const __half* Wh_gx = wh + 2u * 1048576;
    const __half* Wh_ga = wh + 3u * 1048576;
    const __half* Wh_f2 = wh + 4u * 1048576;
    const __half* Wh_b2 = wh + 5u * 1048576;

    cudaFuncSetAttribute(hgemm<true,  false, true>,  cudaFuncAttributeMaxDynamicSharedMemorySize, SMEMSZ);
    cudaFuncSetAttribute(hgemm<true,  false, false>, cudaFuncAttributeMaxDynamicSharedMemorySize, SMEMSZ);
    cudaFuncSetAttribute(hgemm<false, true,  false>, cudaFuncAttributeMaxDynamicSharedMemorySize, SMEMSZ);

    dim3 gp(16, 256);         // pair: (8 N-tiles x 2 sel) x 256 M-tiles
    dim3 gf(8, 256);          // final
    dim3 gsc(NC, 16);         // chunks x (8 fwd + 8 bwd)

    // pack weights to fp16 fragment-pair layout
    wpack<<<dim3(64, 6), 256>>>(Wf1, Wbx, Wgx, Wga, Wf2, Wb2);
    // xh = fp16(gelu(x))
    ew_gelu<<<NE / 4 / 256, 256>>>(x);
    // u = xh@Wf1+bf1 (fp32) ; vh = fp16(xh@Wbx+bbx)
    hgemm<true, false, true><<<gp, 128, SMEMSZ>>>(xh, nullptr, Wh_f1, Wh_bx, bf1, bbx, nullptr, u, (void*)vh);
    // p = vh@Wgx+bgx ; q = vh@Wga+bga (both fp32)
    hgemm<true, false, false><<<gp, 128, SMEMSZ>>>(vh, nullptr, Wh_gx, Wh_ga, bgx, bga, nullptr, p, (void*)q);
    // scans: local (fwd u -> uh fp16; fused gates + bwd -> ph/q), carries, correction
    scan1<<<gsc, 256>>>(a_fwd, a_param);
    scan2<<<64, 256>>>(a_fwd);
    scan3<<<gsc, 256>>>(a_fwd);
    // out = hf@Wf2 + hb@Wb2 + bf2 + bb2 + x
    hgemm<false, true, false><<<gf, 128, SMEMSZ>>>(uh, ph, Wh_f2, Wh_b2, bf2, bb2, x, out, nullptr);
}

// round 14
// speedup vs baseline: 1.5792x; 1.0631x over previous
#include <cuda_runtime.h>
#include <cuda_fp16.h>
#include <cstdint>

// Problem constants
#define Bc   8
#define Sc   4096
#define Dc   1024
#define Mtot 32768            // B*S
#define NE   33554432         // Mtot*Dc elements
#define NC   64               // scan chunks
#define LC   64               // chunk length (NC*LC == Sc)

// -------- scratch (device globals: allocation-free) --------
__device__ __align__(16) float  g_p [NE];   // gate_x pre (fp32)
__device__ __align__(16) float  g_q [NE];   // gate_a pre -> a (fp32)
__device__ __align__(16) __half g_xh[NE];   // gelu(x) fp16
__device__ __align__(16) __half g_vh[NE];   // v fp16
__device__ __align__(16) __half g_uh[NE];   // u -> hf fp16 (in place)
__device__ __align__(16) __half g_ph[NE];   // hb fp16 (local then corrected)
__device__ __align__(16) __half g_Wh[6 * 1024 * 1024]; // frag-pair-packed fp16 weights
__device__ __align__(16) float g_cV [Bc*NC*Dc];   // fwd carries
__device__ __align__(16) float g_cI [Bc*NC*Dc];   // fwd prefixes
__device__ __align__(16) float g_cVb[Bc*NC*Dc];   // bwd carries
__device__ __align__(16) float g_cP [Bc*NC*Dc];   // bwd chunk products
__device__ __align__(16) float g_cIb[Bc*NC*Dc];   // bwd prefixes

// ================= helpers =================
__device__ __forceinline__ void mma16(float* c, const unsigned* a, const unsigned* b) {
    asm volatile(
        "mma.sync.aligned.m16n8k16.row.col.f32.f16.f16.f32 "
        "{%0,%1,%2,%3}, {%4,%5,%6,%7}, {%8,%9}, {%0,%1,%2,%3};\n"
        : "+f"(c[0]), "+f"(c[1]), "+f"(c[2]), "+f"(c[3])
        : "r"(a[0]), "r"(a[1]), "r"(a[2]), "r"(a[3]), "r"(b[0]), "r"(b[1]));
}
__device__ __forceinline__ float gelu1(float x) {
    const float c = 0.7978845608028654f;
    float t = tanhf(c * (x + 0.044715f * x * x * x));
    return 0.5f * x * (1.f + t);
}
__device__ __forceinline__ float sigmoidf(float x) { return 1.f / (1.f + expf(-x)); }
__device__ __forceinline__ uint32_t smem_u32(const void* p) {
    uint32_t a;
    asm("{ .reg .u64 t; cvta.to.shared.u64 t, %1; cvt.u32.u64 %0, t; }" : "=r"(a) : "l"(p));
    return a;
}
__device__ __forceinline__ void cpasync16(uint32_t sdst, const void* gsrc) {
    asm volatile("cp.async.cg.shared.global [%0], [%1], 16;\n" :: "r"(sdst), "l"(gsrc));
}
__device__ __forceinline__ float4 h2tof4(uint2 r) {
    __half2 h0 = *reinterpret_cast<__half2*>(&r.x);
    __half2 h1 = *reinterpret_cast<__half2*>(&r.y);
    return make_float4(__low2float(h0), __high2float(h0),
                       __low2float(h1), __high2float(h1));
}
__device__ __forceinline__ uint2 f4toh2(float4 v) {
    __half2 h0 = __floats2half2_rn(v.x, v.y);
    __half2 h1 = __floats2half2_rn(v.z, v.w);
    uint2 o;
    o.x = *reinterpret_cast<uint32_t*>(&h0);
    o.y = *reinterpret_cast<uint32_t*>(&h1);
    return o;
}

// ================= GEMM (fp16 mma.sync m16n8k16, 64x64 warp tiles, BK=64) ========
// CTA tile 128x128x64, 4 warps, warp tile 64x64, 3-stage cp.async, 2 CTAs/SM.
// As: fp16 [m][k] rows padded to 144B -> LDS.32 frags conflict-free.
// Bs: frag-pair-packed rows (ksj = kk*4+j), 128 n-entries of 8B
//     {B[k0][n],B[k0+1][n],B[k0+8][n],B[k0+9][n]}, k0 = kk*16 + 2j.
//     word8(ksj,n) = ksj*136 + (n ^ ((ksj&3)<<2)). One LDS.64 per B frag.
#define A_BYTES  (128 * 144)            // 18432
#define B_BYTES  (16 * 136 * 8)         // 17408
#define SET_B    (A_BYTES + B_BYTES)    // 35840
#define SMEMSZ   (3 * SET_B)            // 107520

// TWOB: grid.x in [0,16): xb = x&7 N-tile, sel = x>>3 picks (B1,C1,bias1)/(B2,C2,bias2)
// DUAL: K=2048 over (A1,B1) then (A2,B2); epilogue adds bias1+bias2+resid
// C1H/C2H: respective outputs stored as fp16
template <bool TWOB, bool DUAL, bool C1H, bool C2H>
__global__ __launch_bounds__(128, 2)
void hgemm(const __half* __restrict__ A1, const __half* __restrict__ A2,
           const __half* __restrict__ B1, const __half* __restrict__ B2,
           const float* __restrict__ bias1, const float* __restrict__ bias2,
           const float* __restrict__ resid,
           void* __restrict__ C1v, void* __restrict__ C2v)
{
    constexpr int NK = DUAL ? 32 : 16;       // K-tiles of 64
    extern __shared__ float smem[];
    const uint32_t sb = smem_u32(smem);
    const int tid  = threadIdx.x;
    const int lane = tid & 31;
    const int warp = tid >> 5;
    const int wm = warp & 1;        // M half (64 rows)
    const int wn = warp >> 1;       // N half (64 cols)

    const int xb  = TWOB ? (blockIdx.x & 7) : blockIdx.x;
    const int sel = TWOB ? (int)(blockIdx.x >> 3) : 0;
    const int m0 = blockIdx.y * 128;
    const int n0 = xb * 128;
    const __half* Bsel   = (TWOB && sel) ? B2 : B1;
    const float* biassel = (TWOB && sel) ? bias2 : bias1;

    float acc[4][8][4];
#pragma unroll
    for (int i = 0; i < 4; i++)
#pragma unroll
        for (int j = 0; j < 8; j++)
#pragma unroll
            for (int k = 0; k < 4; k++) acc[i][j][k] = 0.f;

    // ---- async tile issue (128 threads) ----
    auto issue = [&](int c) {
        const int slot = c % 3;
        const __half* Ap; const __half* Bp; int cl;
        if (DUAL && c >= 16) { Ap = A2; Bp = B2;   cl = c - 16; }
        else                 { Ap = A1; Bp = Bsel; cl = c; }
        const uint32_t sa = sb + slot * SET_B;
        const uint32_t sB = sa + A_BYTES;
        // A: 128 rows x 64 fp16 (128B) -> 144B-stride rows
#pragma unroll
        for (int i = 0; i < 8; i++) {
            int id = tid + i * 128;
            int r = id >> 3, kq = id & 7;
            cpasync16(sa + (uint32_t)(r * 144 + kq * 16),
                      Ap + (size_t)(m0 + r) * 1024 + cl * 64 + kq * 8);
        }
        // B: 16 packed rows x 128 n x 8B; global row stride 4096 halfs
#pragma unroll
        for (int i = 0; i < 8; i++) {
            int id = tid + i * 128;
            int ksj = id >> 6, ch = id & 63;
            uint32_t w8 = (uint32_t)(ksj * 136 + ((2 * ch) ^ ((ksj & 3) << 2)));
            cpasync16(sB + w8 * 8,
                      Bp + (size_t)(cl * 16 + ksj) * 4096 + (size_t)n0 * 4 + ch * 8);
        }
        asm volatile("cp.async.commit_group;\n");
    };

    auto compute = [&](int slot) {
        const uint32_t* Asw = (const uint32_t*)((const char*)smem + slot * SET_B);
        const uint2*    Bs2 = (const uint2*)((const char*)smem + slot * SET_B + A_BYTES);
        const int r0  = wm * 64 + (lane >> 2);
        const int j   = lane & 3;
        const int ccb = wn * 64 + (lane >> 2);
#pragma unroll
        for (int kk = 0; kk < 4; kk++) {
            unsigned af[4][4], bf[8][2];
#pragma unroll
            for (int mt = 0; mt < 4; mt++) {
                int r = r0 + mt * 16;
                int w0 = r * 36 + kk * 8 + j;
                int w1 = (r + 8) * 36 + kk * 8 + j;
                af[mt][0] = Asw[w0];
                af[mt][1] = Asw[w1];
                af[mt][2] = Asw[w0 + 4];
                af[mt][3] = Asw[w1 + 4];
            }
            const int rowb = (kk * 4 + j) * 136;
#pragma unroll
            for (int nt = 0; nt < 8; nt++) {
                int cc = ccb + nt * 8;
                uint2 bv = Bs2[rowb + (cc ^ (j << 2))];
                bf[nt][0] = bv.x;
                bf[nt][1] = bv.y;
            }
#pragma unroll
            for (int mt = 0; mt < 4; mt++)
#pragma unroll
                for (int nt = 0; nt < 8; nt++)
                    mma16(acc[mt][nt], af[mt], bf[nt]);
        }
    };

    issue(0);
    issue(1);
    for (int k = 0; k < NK; k++) {
        if (k < NK - 1) asm volatile("cp.async.wait_group 1;\n");
        else            asm volatile("cp.async.wait_group 0;\n");
        __syncthreads();
        if (k + 2 < NK) issue(k + 2);
        compute(k % 3);
    }

    // ---- epilogue ----
#pragma unroll
    for (int mt = 0; mt < 4; mt++) {
        int row = m0 + wm * 64 + mt * 16 + (lane >> 2);
#pragma unroll
        for (int nt = 0; nt < 8; nt++) {
            int col = n0 + wn * 64 + nt * 8 + (lane & 3) * 2;
            float b0 = biassel[col], b1 = biassel[col + 1];
            if (DUAL) { b0 += bias2[col]; b1 += bias2[col + 1]; }
            size_t i0 = (size_t)row * 1024 + col;
            size_t i1 = i0 + (size_t)8 * 1024;
            float2 v0 = make_float2(acc[mt][nt][0] + b0, acc[mt][nt][1] + b1);
            float2 v1 = make_float2(acc[mt][nt][2] + b0, acc[mt][nt][3] + b1);
            if (DUAL) {
                float2 x0 = *reinterpret_cast<const float2*>(&resid[i0]);
                float2 x1 = *reinterpret_cast<const float2*>(&resid[i1]);
                v0.x += x0.x; v0.y += x0.y; v1.x += x1.x; v1.y += x1.y;
            }
            const bool useC2 = TWOB && sel;
            void* Cp = useC2 ? C2v : C1v;
            const bool asH = useC2 ? C2H : C1H;
            if (asH) {
                __half* Ch = (__half*)Cp;
                *reinterpret_cast<__half2*>(&Ch[i0]) = __floats2half2_rn(v0.x, v0.y);
                *reinterpret_cast<__half2*>(&Ch[i1]) = __floats2half2_rn(v1.x, v1.y);
            } else {
                float* Cf = (float*)Cp;
                *reinterpret_cast<float2*>(&Cf[i0]) = v0;
                *reinterpret_cast<float2*>(&Cf[i1]) = v1;
            }
        }
    }
}

// ================= weight frag-pair pack to fp16 =================
__global__ void wpack(const float* __restrict__ w0, const float* __restrict__ w1,
                      const float* __restrict__ w2, const float* __restrict__ w3,
                      const float* __restrict__ w4, const float* __restrict__ w5)
{
    const float* srcs[6] = {w0, w1, w2, w3, w4, w5};
    const float* src = srcs[blockIdx.y];
    __half* dst = g_Wh + (size_t)blockIdx.y * 1048576;
    const int kg = blockIdx.x;          // 0..63
    const int t = threadIdx.x;          // 0..255
#pragma unroll
    for (int j = 0; j < 4; j++) {
#pragma unroll
        for (int nn = 0; nn < 4; nn++) {
            int n = nn * 256 + t;
            float f0 = src[(size_t)(kg * 16 + 2 * j    ) * 1024 + n];
            float f1 = src[(size_t)(kg * 16 + 2 * j + 1) * 1024 + n];
            float f2 = src[(size_t)(kg * 16 + 2 * j + 8) * 1024 + n];
            float f3 = src[(size_t)(kg * 16 + 2 * j + 9) * 1024 + n];
            __half2 p0 = __floats2half2_rn(f0, f1);
            __half2 p1 = __floats2half2_rn(f2, f3);
            uint2 o;
            o.x = *reinterpret_cast<uint32_t*>(&p0);
            o.y = *reinterpret_cast<uint32_t*>(&p1);
            *reinterpret_cast<uint2*>(&dst[((size_t)(kg * 4 + j) * 1024 + n) * 4]) = o;
        }
    }
}

// ================= elementwise =================
__global__ void ew_gelu(const float* __restrict__ x) {
    int i = blockIdx.x * 256 + threadIdx.x;
    float4 v = reinterpret_cast<const float4*>(x)[i];
    __half2 h0 = __floats2half2_rn(gelu1(v.x), gelu1(v.y));
    __half2 h1 = __floats2half2_rn(gelu1(v.z), gelu1(v.w));
    uint2 o;
    o.x = *reinterpret_cast<uint32_t*>(&h0);
    o.y = *reinterpret_cast<uint32_t*>(&h1);
    reinterpret_cast<uint2*>(g_xh)[i] = o;
}

// ================= scans (float4 over d; split fwd/bwd kernels for streams) ======
// fwd phase 1: local chunk scan in place on uh (fp16). grid (NC, 8)
__global__ void scan1f(const float* __restrict__ a_fwd) {
    const int d4 = threadIdx.x;
    const int c = blockIdx.x, b = blockIdx.y;
    float4 a = reinterpret_cast<const float4*>(a_fwd)[d4];
    int idx = ((b * Sc + c * LC) * Dc) / 4 + d4;
    float4 h = make_float4(0.f, 0.f, 0.f, 0.f);
#pragma unroll 4
    for (int t = 0; t < LC; t++) {
        float4 uv = h2tof4(reinterpret_cast<const uint2*>(g_uh)[idx]);
        h.x = fmaf(a.x, h.x, uv.x); h.y = fmaf(a.y, h.y, uv.y);
        h.z = fmaf(a.z, h.z, uv.z); h.w = fmaf(a.w, h.w, uv.w);
        reinterpret_cast<uint2*>(g_uh)[idx] = f4toh2(h);
        idx += 256;
    }
    reinterpret_cast<float4*>(g_cV)[(b * NC + c) * 256 + d4] = h;
}
// fwd phase 2: carry prefix. 32 blocks x 256
__global__ void scan2f(const float* __restrict__ a_fwd) {
    int g = blockIdx.x * 256 + threadIdx.x;
    int b = g >> 10, d = g & 1023;
    float a = a_fwd[d];
    float aL = a;
#pragma unroll
    for (int i = 0; i < 6; i++) aL *= aL;     // a^64 (LC=64)
    float H = 0.f;
    for (int c = 0; c < NC; c++) {
        int o = (b * NC + c) * Dc + d;
        float cv = g_cV[o];
        g_cI[o] = H;
        H = fmaf(aL, H, cv);
    }
}
// fwd phase 3: apply carries in uh. grid (NC, 8)
__global__ void scan3f(const float* __restrict__ a_fwd) {
    const int d4 = threadIdx.x;
    const int c = blockIdx.x, b = blockIdx.y;
    if (c == 0) return;
    float4 a = reinterpret_cast<const float4*>(a_fwd)[d4];
    float4 H = reinterpret_cast<const float4*>(g_cI)[(b * NC + c) * 256 + d4];
    int idx = ((b * Sc + c * LC) * Dc) / 4 + d4;
    float4 pw = a;
#pragma unroll 4
    for (int t = 0; t < LC; t++) {
        float4 uv = h2tof4(reinterpret_cast<const uint2*>(g_uh)[idx]);
        uv.x = fmaf(pw.x, H.x, uv.x); uv.y = fmaf(pw.y, H.y, uv.y);
        uv.z = fmaf(pw.z, H.z, uv.z); uv.w = fmaf(pw.w, H.w, uv.w);
        reinterpret_cast<uint2*>(g_uh)[idx] = f4toh2(uv);
        pw.x *= a.x; pw.y *= a.y; pw.z *= a.z; pw.w *= a.w;
        idx += 256;
    }
}
// bwd phase 1: fused gates + reverse local scan. grid (NC, 8)
__global__ void scan1b(const float* __restrict__ a_param) {
    const int d4 = threadIdx.x;
    const int c = blockIdx.x, b = blockIdx.y;
    float4 ap = reinterpret_cast<const float4*>(a_param)[d4];
    float4 sp = make_float4(log1pf(expf(ap.x)), log1pf(expf(ap.y)),
                            log1pf(expf(ap.z)), log1pf(expf(ap.w)));
    int idx = ((b * Sc + c * LC + LC - 1) * Dc) / 4 + d4;
    float4 h = make_float4(0.f, 0.f, 0.f, 0.f);
    float4 P = make_float4(1.f, 1.f, 1.f, 1.f);
#pragma unroll 4
    for (int t = 0; t < LC; t++) {
        float4 pv = reinterpret_cast<const float4*>(g_p)[idx];
        float4 qv = reinterpret_cast<const float4*>(g_q)[idx];
        float4 vv = h2tof4(reinterpret_cast<const uint2*>(g_vh)[idx]);
        float4 ao;
#define GB(PV,QV,VV,SP,H,PP,AO) { \
        float gx = sigmoidf(PV); float ga = sigmoidf(QV); \
        float a_ = expf(-8.f * ga * (SP)); \
        float si = sqrtf(fmaxf(1.f - a_*a_, 0.f)) * gx * (VV); \
        H = fmaf(a_, H, si); PP *= a_; AO = a_; }
        GB(pv.x, qv.x, vv.x, sp.x, h.x, P.x, ao.x)
        GB(pv.y, qv.y, vv.y, sp.y, h.y, P.y, ao.y)
        GB(pv.z, qv.z, vv.z, sp.z, h.z, P.z, ao.z)
        GB(pv.w, qv.w, vv.w, sp.w, h.w, P.w, ao.w)
#undef GB
        reinterpret_cast<float4*>(g_q)[idx] = ao;
        reinterpret_cast<uint2*>(g_ph)[idx] = f4toh2(h);
        idx -= 256;
    }
    int o = (b * NC + c) * 256 + d4;
    reinterpret_cast<float4*>(g_cVb)[o] = h;
    reinterpret_cast<float4*>(g_cP)[o] = P;
}
// bwd phase 2: carry prefix (reverse). 32 blocks x 256
__global__ void scan2b() {
    int g = blockIdx.x * 256 + threadIdx.x;
    int b = g >> 10, d = g & 1023;
    float H = 0.f;
    for (int c = NC - 1; c >= 0; c--) {
        int o = (b * NC + c) * Dc + d;
        float cv = g_cVb[o], cp = g_cP[o];
        g_cIb[o] = H;
        H = fmaf(cp, H, cv);
    }
}
// bwd phase 3: apply carries in ph. grid (NC, 8)
__global__ void scan3b() {
    const int d4 = threadIdx.x;
    const int c = blockIdx.x, b = blockIdx.y;
    if (c == NC - 1) return;
    float4 H = reinterpret_cast<const float4*>(g_cIb)[(b * NC + c) * 256 + d4];
    int idx = ((b * Sc + c * LC + LC - 1) * Dc) / 4 + d4;
    float4 P = make_float4(1.f, 1.f, 1.f, 1.f);
#pragma unroll 4
    for (int t = 0; t < LC; t++) {
        float4 at = reinterpret_cast<const float4*>(g_q)[idx];
        float4 pv = h2tof4(reinterpret_cast<const uint2*>(g_ph)[idx]);
        P.x *= at.x; P.y *= at.y; P.z *= at.z; P.w *= at.w;
        pv.x = fmaf(P.x, H.x, pv.x); pv.y = fmaf(P.y, H.y, pv.y);
        pv.z = fmaf(P.z, H.z, pv.z); pv.w = fmaf(P.w, H.w, pv.w);
        reinterpret_cast<uint2*>(g_ph)[idx] = f4toh2(pv);
        idx -= 256;
    }
}

// ================= launch =================
extern "C" void kernel_launch(void* const* d_in, const int* in_sizes, int n_in,
                              void* d_out, int out_size)
{
    const float* x       = (const float*)d_in[0];
    const float* a_fwd   = (const float*)d_in[1];
    const float* Wf1     = (const float*)d_in[2];
    const float* bf1     = (const float*)d_in[3];
    const float* Wf2     = (const float*)d_in[4];
    const float* bf2     = (const float*)d_in[5];
    const float* Wbx     = (const float*)d_in[6];
    const float* bbx     = (const float*)d_in[7];
    const float* Wgx     = (const float*)d_in[8];
    const float* bgx     = (const float*)d_in[9];
    const float* Wga     = (const float*)d_in[10];
    const float* bga     = (const float*)d_in[11];
    const float* a_param = (const float*)d_in[12];
    const float* Wb2     = (const float*)d_in[13];
    const float* bb2     = (const float*)d_in[14];
    float* out = (float*)d_out;

    float *p, *q;
    __half *xh, *vh, *uh, *ph, *wh;
    cudaGetSymbolAddress((void**)&p,  g_p);
    cudaGetSymbolAddress((void**)&q,  g_q);
    cudaGetSymbolAddress((void**)&xh, g_xh);
    cudaGetSymbolAddress((void**)&vh, g_vh);
    cudaGetSymbolAddress((void**)&uh, g_uh);
    cudaGetSymbolAddress((void**)&ph, g_ph);
    cudaGetSymbolAddress((void**)&wh, g_Wh);
    const __half* Wh_f1 = wh + 0u * 1048576;
    const __half* Wh_bx = wh + 1u * 1048576;
    const __half* Wh_gx = wh + 2u * 1048576;
    const __half* Wh_ga = wh + 3u * 1048576;
    const __half* Wh_f2 = wh + 4u * 1048576;
    const __half* Wh_b2 = wh + 5u * 1048576;

    // side stream + fork/join events (host objects; created once, no device mem)
    static cudaStream_t s1 = nullptr;
    static cudaEvent_t e1 = nullptr, e2 = nullptr;
    if (!s1) {
        cudaStreamCreateWithFlags(&s1, cudaStreamNonBlocking);
        cudaEventCreateWithFlags(&e1, cudaEventDisableTiming);
        cudaEventCreateWithFlags(&e2, cudaEventDisableTiming);
    }

    cudaFuncSetAttribute(hgemm<true,  false, true,  true>,  cudaFuncAttributeMaxDynamicSharedMemorySize, SMEMSZ);
    cudaFuncSetAttribute(hgemm<true,  false, false, false>, cudaFuncAttributeMaxDynamicSharedMemorySize, SMEMSZ);
    cudaFuncSetAttribute(hgemm<false, true,  false, false>, cudaFuncAttributeMaxDynamicSharedMemorySize, SMEMSZ);

    dim3 gp(16, 256);         // pair: (8 N-tiles x 2 sel) x 256 M-tiles
    dim3 gf(8, 256);          // final
    dim3 gsc(NC, 8);          // chunks x batch

    // pack weights to fp16 fragment-pair layout
    wpack<<<dim3(64, 6), 256>>>(Wf1, Wbx, Wgx, Wga, Wf2, Wb2);
    // xh = fp16(gelu(x))
    ew_gelu<<<NE / 4 / 256, 256>>>(x);
    // uh = fp16(xh@Wf1+bf1) ; vh = fp16(xh@Wbx+bbx)
    hgemm<true, false, true, true><<<gp, 128, SMEMSZ>>>(xh, nullptr, Wh_f1, Wh_bx, bf1, bbx, nullptr, (void*)uh, (void*)vh);
    cudaEventRecord(e1, 0);

    // forked fwd scan chain on s1 (depends only on GEMM1)
    cudaStreamWaitEvent(s1, e1, 0);
    scan1f<<<gsc, 256, 0, s1>>>(a_fwd);
    scan2f<<<32, 256, 0, s1>>>(a_fwd);
    scan3f<<<gsc, 256, 0, s1>>>(a_fwd);
    cudaEventRecord(e2, s1);

    // main stream: p = vh@Wgx+bgx ; q = vh@Wga+bga, then bwd scans
    hgemm<true, false, false, false><<<gp, 128, SMEMSZ>>>(vh, nullptr, Wh_gx, Wh_ga, bgx, bga, nullptr, (void*)p, (void*)q);
    scan1b<<<gsc, 256>>>(a_param);
    scan2b<<<32, 256>>>();
    scan3b<<<gsc, 256>>>();

    // join fwd chain, then final: out = hf@Wf2 + hb@Wb2 + bf2 + bb2 + x
    cudaStreamWaitEvent(0, e2, 0);
    hgemm<false, true, false, false><<<gf, 128, SMEMSZ>>>(uh, ph, Wh_f2, Wh_b2, bf2, bb2, x, (void*)out, nullptr);
}